// round 14
// baseline (speedup 1.0000x reference)
#include <cuda_runtime.h>
#include <cuda_fp16.h>
#include <cstdint>

// Problem dims
#define BATCH 8
#define SEQ   2048
#define EMB   1024
#define HEAD  128
#define MROWS (BATCH * SEQ)     // 16384
#define NTILES (MROWS / 128)    // 128 (retention tiling)
#define TILE_ELE (128 * 128)

// fp16 projected tensors, row-major per 128x128 tile.
// Q: [m][h]. K: [n][h]. V: TRANSPOSED [h][n].
__device__ __half g_q[NTILES * TILE_ELE];
__device__ __half g_k[NTILES * TILE_ELE];
__device__ __half g_v[NTILES * TILE_ELE];

// fp16 weights: [w][n][k], k contiguous
__device__ __half g_w[3 * 128 * 1024];

// Chunk schedule (proven): 24 chunks per batch, longest first.
__constant__ int c_qt[24] = {15,15,14, 7,14,13,13,12, 6,12,11,11,10, 5,10, 9, 9, 8, 4, 8, 3, 2, 1, 0};
__constant__ int c_j0[24] = { 0, 8, 0, 0, 8, 0, 7, 0, 0, 7, 0, 6, 0, 0, 6, 0, 5, 0, 0, 5, 0, 0, 0, 0};
__constant__ int c_j1[24] = { 8,16, 8, 8,15, 7,14, 7, 7,13, 6,12, 6, 6,11, 5,10, 5, 5, 9, 4, 3, 2, 1};

// ---------------------------------------------------------------------------
// PTX helpers (family-generic)
// ---------------------------------------------------------------------------
__device__ __forceinline__ uint32_t smem_u32(const void* p) {
    uint32_t a;
    asm("{ .reg .u64 t; cvta.to.shared.u64 t, %1; cvt.u32.u64 %0, t; }"
        : "=r"(a) : "l"(p));
    return a;
}

__device__ __forceinline__ void mma16816(float* c,
    uint32_t a0, uint32_t a1, uint32_t a2, uint32_t a3,
    uint32_t b0, uint32_t b1)
{
    asm volatile(
        "mma.sync.aligned.m16n8k16.row.col.f32.f16.f16.f32 "
        "{%0,%1,%2,%3}, {%4,%5,%6,%7}, {%8,%9}, {%0,%1,%2,%3};"
        : "+f"(c[0]), "+f"(c[1]), "+f"(c[2]), "+f"(c[3])
        : "r"(a0), "r"(a1), "r"(a2), "r"(a3), "r"(b0), "r"(b1));
}

__device__ __forceinline__ void ldm_x4(uint32_t& r0, uint32_t& r1,
                                       uint32_t& r2, uint32_t& r3, uint32_t addr)
{
    asm volatile("ldmatrix.sync.aligned.m8n8.x4.shared.b16 {%0,%1,%2,%3}, [%4];"
                 : "=r"(r0), "=r"(r1), "=r"(r2), "=r"(r3) : "r"(addr));
}

#define CP_ASYNC16(dst, src) \
    asm volatile("cp.async.cg.shared.global [%0], [%1], 16;" :: "r"(dst), "l"(src))
#define CP_COMMIT() asm volatile("cp.async.commit_group;" ::: "memory")
#define CP_WAIT(n)  asm volatile("cp.async.wait_group %0;" :: "n"(n) : "memory")

#define RED_ADD_F32(addr, val) \
    asm volatile("red.global.add.f32 [%0], %1;" :: "l"(addr), "f"(val) : "memory")

__device__ __forceinline__ uint32_t cvt2h(float a0, float a1) {
    __half2 h = __float22half2_rn(make_float2(a0, a1));
    return *reinterpret_cast<uint32_t*>(&h);
}

// ---------------------------------------------------------------------------
// Kernel 0: convert W to fp16, layout [w][n][k]
// ---------------------------------------------------------------------------
__global__ __launch_bounds__(256) void prep_w(
    const float* __restrict__ wq, const float* __restrict__ wk,
    const float* __restrict__ wv)
{
    int u = blockIdx.x * 256 + threadIdx.x;
    int w = u >> 16;
    int rem = u & 65535;
    int n = rem >> 9;
    int kp = (rem & 511) * 2;
    const float* W = (w == 0) ? wq : (w == 1) ? wk : wv;
    float w0 = W[(size_t)kp * HEAD + n];
    float w1 = W[(size_t)(kp + 1) * HEAD + n];
    *(uint32_t*)&g_w[((size_t)w * 128 + n) * 1024 + kp] = cvt2h(w0, w1);
}

// ---------------------------------------------------------------------------
// Kernel 1: projection GEMM  C = A @ W, fp16 single-product.
// 64x128 tile per CTA, 8 warps of 32x32 (acc=32 regs) -> 2 CTAs/SM without
// spills. Round-11 k-pipeline: persistent areg prefetch + W double-buffer.
// grid = (MROWS/64, 3) = (256, 3).
// ---------------------------------------------------------------------------
#define PKPAD 72
#define PABUF_A (64 * PKPAD * 2)    // 9216 B per A stage
#define PABUF_W (128 * PKPAD * 2)   // 18432 B per W stage
// smem: A0 0, A1 +PABUF_A, W0 +2*PABUF_A, W1 +2*PABUF_A+PABUF_W
#define PSM_TOTAL (2 * PABUF_A + 2 * PABUF_W)   // 55296 (x2 CTAs = 110592)

__device__ __forceinline__ void warp_gemm_proj64(float acc[2][4][4],
    uint32_t sA, uint32_t sW, uint32_t a_lane, uint32_t b_lane)
{
#pragma unroll
    for (int ks = 0; ks < 4; ks++) {
        const uint32_t kso = (uint32_t)(ks * 16) * 2;
        uint32_t ah[2][4];
#pragma unroll
        for (int mt = 0; mt < 2; mt++) {
            const uint32_t ao = a_lane + (uint32_t)(mt * 16 * PKPAD) * 2 + kso;
            ldm_x4(ah[mt][0], ah[mt][1], ah[mt][2], ah[mt][3], sA + ao);
        }
#pragma unroll
        for (int np = 0; np < 2; np++) {
            const uint32_t bo = b_lane + (uint32_t)(np * 16 * PKPAD) * 2 + kso;
            uint32_t bh[4];
            ldm_x4(bh[0], bh[1], bh[2], bh[3], sW + bo);
#pragma unroll
            for (int mt = 0; mt < 2; mt++) {
                mma16816(acc[mt][2*np],   ah[mt][0], ah[mt][1], ah[mt][2], ah[mt][3], bh[0], bh[1]);
                mma16816(acc[mt][2*np+1], ah[mt][0], ah[mt][1], ah[mt][2], ah[mt][3], bh[2], bh[3]);
            }
        }
    }
}

__global__ __launch_bounds__(256, 2) void proj_tc(
    const float* __restrict__ in_key,
    const float* __restrict__ in_query,
    const float* __restrict__ in_value)
{
    extern __shared__ __align__(16) char psm[];
    const uint32_t sb = smem_u32(psm);
    const uint32_t sW0 = sb + 2 * PABUF_A;

    const float* A;
    const int p = blockIdx.y;
    if (p == 0)      A = in_query;
    else if (p == 1) A = in_key;
    else             A = in_value;

    const int tid  = threadIdx.x;
    const int wid  = tid >> 5, lane = tid & 31;
    const int g    = lane >> 2, t = lane & 3;
    const int mbase = (wid & 1) * 32;       // 2 row groups of 32
    const int nbase = (wid >> 1) * 32;      // 4 col groups of 32
    const int tile64 = blockIdx.x;          // 64-row tile index (0..255)
    const int rowBase = tile64 * 64;

    const uint32_t a_lane = ((mbase + (lane & 15)) * PKPAD + (lane >> 4) * 8) * 2;
    const uint32_t b_lane = ((nbase + (lane & 7) + ((lane >> 4) << 3)) * PKPAD
                             + ((lane >> 3) & 1) * 8) * 2;

    const int aRow0 = tid >> 4;             // 0..15, rows +16 apart (4 iters -> 64)
    const int aC4   = (tid & 15) * 4;

    float acc[2][4][4];
#pragma unroll
    for (int i = 0; i < 2; i++)
#pragma unroll
        for (int j = 0; j < 4; j++)
#pragma unroll
            for (int q = 0; q < 4; q++) acc[i][j][q] = 0.0f;

    const __half* wsrc = g_w + (size_t)p * 128 * 1024;

    auto cpa_w = [&](int kb, int s) {
        uint32_t dw = sW0 + s * PABUF_W;
#pragma unroll
        for (int it = 0; it < 4; it++) {
            int u = tid + it * 256;
            int row = u >> 3, c = u & 7;
            uint32_t doff = (uint32_t)(row * PKPAD + c * 8) * 2;
            size_t soff = (size_t)row * 1024 + kb * 64 + c * 8;
            CP_ASYNC16(dw + doff, (const char*)(wsrc + soff));
        }
        CP_COMMIT();
    };

    auto conv_a = [&](const float4* areg, int s) {
        const uint32_t dA = sb + s * PABUF_A;
#pragma unroll
        for (int it = 0; it < 4; it++) {
            uint32_t h0 = cvt2h(areg[it].x, areg[it].y);
            uint32_t h1 = cvt2h(areg[it].z, areg[it].w);
            uint32_t doff = (uint32_t)((aRow0 + it * 16) * PKPAD + aC4) * 2;
            asm volatile("st.shared.v2.b32 [%0], {%1,%2};" :: "r"(dA + doff), "r"(h0), "r"(h1));
        }
    };

    float4 areg[4];
#pragma unroll
    for (int it = 0; it < 4; it++)
        areg[it] = *(const float4*)&A[(size_t)(rowBase + aRow0 + it * 16) * EMB + aC4];
    conv_a(areg, 0);
#pragma unroll
    for (int it = 0; it < 4; it++)
        areg[it] = *(const float4*)&A[(size_t)(rowBase + aRow0 + it * 16) * EMB + 64 + aC4];
    cpa_w(0, 0);

    for (int kb = 0; kb < 16; kb++) {
        CP_WAIT(0);
        __syncthreads();

        if (kb < 15) {
            cpa_w(kb + 1, (kb + 1) & 1);
            conv_a(areg, (kb + 1) & 1);
        }
        if (kb < 14) {
            const int k0n = (kb + 2) * 64;
#pragma unroll
            for (int it = 0; it < 4; it++)
                areg[it] = *(const float4*)&A[(size_t)(rowBase + aRow0 + it * 16) * EMB + k0n + aC4];
        }

        const uint32_t sA = sb + (kb & 1) * PABUF_A;
        const uint32_t sW = sW0 + (kb & 1) * PABUF_W;
        warp_gemm_proj64(acc, sA, sW, a_lane, b_lane);
    }

    // Epilogue: destination is the 128x128 retention tile layout.
    const int tile128 = tile64 >> 1;            // retention tile
    const int rowOff  = (tile64 & 1) * 64;      // row offset within it
    const size_t base = (size_t)tile128 * TILE_ELE;

    if (p != 2) {
        __half* dst = (p == 0) ? g_q : g_k;
#pragma unroll
        for (int mt = 0; mt < 2; mt++)
#pragma unroll
            for (int nt = 0; nt < 4; nt++) {
                int r0 = rowOff + mbase + mt * 16 + g;
                int c  = nbase + nt * 8 + t * 2;
                *(uint32_t*)(dst + base + (size_t)r0 * 128 + c) =
                    cvt2h(acc[mt][nt][0], acc[mt][nt][1]);
                *(uint32_t*)(dst + base + (size_t)(r0 + 8) * 128 + c) =
                    cvt2h(acc[mt][nt][2], acc[mt][nt][3]);
            }
    } else {
        // V: transposed [h][n] within the 128x128 tile
#pragma unroll
        for (int mt = 0; mt < 2; mt++)
#pragma unroll
            for (int nt = 0; nt < 4; nt++)
#pragma unroll
                for (int q = 0; q < 4; q++) {
                    int row = rowOff + mbase + mt * 16 + g + (q >> 1) * 8;  // n index
                    int col = nbase + nt * 8 + t * 2 + (q & 1);             // h index
                    g_v[base + (size_t)col * 128 + row] = __float2half(acc[mt][nt][q]);
                }
    }
}

// ---------------------------------------------------------------------------
// Kernel 2: fused causal retention (round-11 proven core, round-13 epilogue).
// ---------------------------------------------------------------------------
#define KPAD 136
#define RB (128 * KPAD * 2)
#define SMR_BYTES (5 * RB)          // 174080: Q, K0, K1, V0, V1

__device__ __forceinline__ void cpa_tile(uint32_t dst, const __half* __restrict__ src,
                                         int tid) {
#pragma unroll
    for (int it = 0; it < 8; it++) {
        int u = tid + it * 256;
        int row = u >> 4, c = u & 15;
        CP_ASYNC16(dst + (uint32_t)(row * KPAD + c * 8) * 2, (const char*)src + (size_t)u * 16);
    }
}

__global__ __launch_bounds__(256) void retention_tc(float* __restrict__ out)
{
    extern __shared__ __align__(16) char smraw[];
    const uint32_t sb = smem_u32(smraw);
    const uint32_t sQ  = sb;
    const uint32_t sK0 = sb + RB;
    const uint32_t sV0 = sb + 3*RB;

    const int tid  = threadIdx.x;
    const int wid  = tid >> 5, lane = tid & 31;
    const int g    = lane >> 2, t = lane & 3;

    const int b   = blockIdx.x;
    const int cid = blockIdx.y;
    const int qt  = c_qt[cid];
    const int j0  = c_j0[cid];
    const int j1  = c_j1[cid];
    const int qtile = b * 16 + qt;

    const uint32_t a_lane = (uint32_t)((16 * wid + (lane & 15)) * KPAD + (lane >> 4) * 8) * 2;
    const uint32_t b_lane = (uint32_t)(((lane & 7) + ((lane >> 4) << 3)) * KPAD
                                       + ((lane >> 3) & 1) * 8) * 2;

    cpa_tile(sQ, g_q + (size_t)qtile * TILE_ELE, tid);
    {
        const size_t kt = (size_t)(b * 16 + j0) * TILE_ELE;
        cpa_tile(sK0 + (uint32_t)(j0 & 1) * RB, g_k + kt, tid);
        cpa_tile(sV0 + (uint32_t)(j0 & 1) * RB, g_v + kt, tid);
    }
    CP_COMMIT();
    CP_WAIT(0);
    __syncthreads();

    float oacc[16][4];
#pragma unroll
    for (int i = 0; i < 16; i++)
#pragma unroll
        for (int q = 0; q < 4; q++) oacc[i][q] = 0.0f;

    for (int j = j0; j < j1; j++) {
        if (j + 1 < j1) {
            const size_t kt = (size_t)(b * 16 + j + 1) * TILE_ELE;
            cpa_tile(sK0 + (uint32_t)((j + 1) & 1) * RB, g_k + kt, tid);
            cpa_tile(sV0 + (uint32_t)((j + 1) & 1) * RB, g_v + kt, tid);
            CP_COMMIT();
        }

        const uint32_t sKc = sK0 + (uint32_t)(j & 1) * RB;
        const uint32_t sVc = sV0 + (uint32_t)(j & 1) * RB;

        // GEMM1: S = Q K^T
        float sacc[16][4];
#pragma unroll
        for (int i = 0; i < 16; i++)
#pragma unroll
            for (int q = 0; q < 4; q++) sacc[i][q] = 0.0f;

#pragma unroll 2
        for (int ks = 0; ks < 8; ks++) {
            const uint32_t kso = (uint32_t)(ks * 16) * 2;
            uint32_t ah[4];
            ldm_x4(ah[0], ah[1], ah[2], ah[3], sQ + a_lane + kso);
#pragma unroll
            for (int nb = 0; nb < 8; nb++) {
                const uint32_t boff = b_lane + (uint32_t)(nb * 16 * KPAD) * 2 + kso;
                uint32_t bh[4];
                ldm_x4(bh[0], bh[1], bh[2], bh[3], sKc + boff);
                mma16816(sacc[2*nb],   ah[0], ah[1], ah[2], ah[3], bh[0], bh[1]);
                mma16816(sacc[2*nb+1], ah[0], ah[1], ah[2], ah[3], bh[2], bh[3]);
            }
        }

        // Causal mask on diagonal tile
        if (j == qt) {
            const int r0 = 16 * wid + g;
#pragma unroll
            for (int nt = 0; nt < 16; nt++) {
                const int c0 = nt * 8 + t * 2;
                if (c0     > r0)     sacc[nt][0] = 0.0f;
                if (c0 + 1 > r0)     sacc[nt][1] = 0.0f;
                if (c0     > r0 + 8) sacc[nt][2] = 0.0f;
                if (c0 + 1 > r0 + 8) sacc[nt][3] = 0.0f;
            }
        }

        // GEMM2: O += S V (S in registers)
#pragma unroll
        for (int ks = 0; ks < 8; ks++) {
            uint32_t sh[4];
            sh[0] = cvt2h(sacc[2*ks][0],   sacc[2*ks][1]);
            sh[1] = cvt2h(sacc[2*ks][2],   sacc[2*ks][3]);
            sh[2] = cvt2h(sacc[2*ks+1][0], sacc[2*ks+1][1]);
            sh[3] = cvt2h(sacc[2*ks+1][2], sacc[2*ks+1][3]);
            const uint32_t kso = (uint32_t)(ks * 16) * 2;
#pragma unroll
            for (int hb = 0; hb < 8; hb++) {
                const uint32_t boff = b_lane + (uint32_t)(hb * 16 * KPAD) * 2 + kso;
                uint32_t vh[4];
                ldm_x4(vh[0], vh[1], vh[2], vh[3], sVc + boff);
                mma16816(oacc[2*hb],   sh[0], sh[1], sh[2], sh[3], vh[0], vh[1]);
                mma16816(oacc[2*hb+1], sh[0], sh[1], sh[2], sh[3], vh[2], vh[3]);
            }
        }

        if (j + 1 < j1) {
            CP_WAIT(0);
            __syncthreads();
        }
    }

    // Epilogue
    const int r0 = 16 * wid + g;
    const size_t rowbase = (size_t)b * SEQ + (size_t)qt * 128;
    if (qt < 8) {
#pragma unroll
        for (int ht = 0; ht < 16; ht++) {
            int c = ht * 8 + t * 2;
            *(float2*)&out[(rowbase + r0) * HEAD + c]     = make_float2(oacc[ht][0], oacc[ht][1]);
            *(float2*)&out[(rowbase + r0 + 8) * HEAD + c] = make_float2(oacc[ht][2], oacc[ht][3]);
        }
    } else {
#pragma unroll
        for (int ht = 0; ht < 16; ht++) {
            int c = ht * 8 + t * 2;
            float* p0 = &out[(rowbase + r0) * HEAD + c];
            float* p1 = &out[(rowbase + r0 + 8) * HEAD + c];
            RED_ADD_F32(p0,     oacc[ht][0]);
            RED_ADD_F32(p0 + 1, oacc[ht][1]);
            RED_ADD_F32(p1,     oacc[ht][2]);
            RED_ADD_F32(p1 + 1, oacc[ht][3]);
        }
    }
}

// ---------------------------------------------------------------------------
// Launch
// ---------------------------------------------------------------------------
extern "C" void kernel_launch(void* const* d_in, const int* in_sizes, int n_in,
                              void* d_out, int out_size)
{
    const float* key   = (const float*)d_in[0];
    const float* query = (const float*)d_in[1];
    const float* value = (const float*)d_in[2];
    const float* w_q   = (const float*)d_in[3];
    const float* w_k   = (const float*)d_in[4];
    const float* w_v   = (const float*)d_in[5];
    float* out = (float*)d_out;

    // Zero-init output: required by the red.add split-K path (qt >= 8 tiles).
    cudaMemsetAsync(out, 0, (size_t)out_size * sizeof(float));

    prep_w<<<768, 256>>>(w_q, w_k, w_v);

    cudaFuncSetAttribute(proj_tc,
                         cudaFuncAttributeMaxDynamicSharedMemorySize, PSM_TOTAL);
    dim3 g1(MROWS / 64, 3);
    proj_tc<<<g1, 256, PSM_TOTAL>>>(key, query, value);

    cudaFuncSetAttribute(retention_tc,
                         cudaFuncAttributeMaxDynamicSharedMemorySize, SMR_BYTES);
    dim3 g2(BATCH, 24);
    retention_tc<<<g2, 256, SMR_BYTES>>>(out);
}

// round 15
// speedup vs baseline: 1.0097x; 1.0097x over previous
#include <cuda_runtime.h>
#include <cuda_fp16.h>
#include <cstdint>

// Problem dims
#define BATCH 8
#define SEQ   2048
#define EMB   1024
#define HEAD  128
#define MROWS (BATCH * SEQ)     // 16384
#define NTILES (MROWS / 128)    // 128
#define TILE_ELE (128 * 128)

// fp16 projected tensors, row-major per 128x128 tile.
// Q: [m][h]. K: [n][h]. V: TRANSPOSED [h][n].
__device__ __half g_q[NTILES * TILE_ELE];
__device__ __half g_k[NTILES * TILE_ELE];
__device__ __half g_v[NTILES * TILE_ELE];

// fp16 weights: [w][n][k], k contiguous
__device__ __half g_w[3 * 128 * 1024];

// Chunk schedule (proven): 24 chunks per batch, longest first.
__constant__ int c_qt[24] = {15,15,14, 7,14,13,13,12, 6,12,11,11,10, 5,10, 9, 9, 8, 4, 8, 3, 2, 1, 0};
__constant__ int c_j0[24] = { 0, 8, 0, 0, 8, 0, 7, 0, 0, 7, 0, 6, 0, 0, 6, 0, 5, 0, 0, 5, 0, 0, 0, 0};
__constant__ int c_j1[24] = { 8,16, 8, 8,15, 7,14, 7, 7,13, 6,12, 6, 6,11, 5,10, 5, 5, 9, 4, 3, 2, 1};

// ---------------------------------------------------------------------------
// PTX helpers (family-generic)
// ---------------------------------------------------------------------------
__device__ __forceinline__ uint32_t smem_u32(const void* p) {
    uint32_t a;
    asm("{ .reg .u64 t; cvta.to.shared.u64 t, %1; cvt.u32.u64 %0, t; }"
        : "=r"(a) : "l"(p));
    return a;
}

__device__ __forceinline__ void mma16816(float* c,
    uint32_t a0, uint32_t a1, uint32_t a2, uint32_t a3,
    uint32_t b0, uint32_t b1)
{
    asm volatile(
        "mma.sync.aligned.m16n8k16.row.col.f32.f16.f16.f32 "
        "{%0,%1,%2,%3}, {%4,%5,%6,%7}, {%8,%9}, {%0,%1,%2,%3};"
        : "+f"(c[0]), "+f"(c[1]), "+f"(c[2]), "+f"(c[3])
        : "r"(a0), "r"(a1), "r"(a2), "r"(a3), "r"(b0), "r"(b1));
}

__device__ __forceinline__ void ldm_x4(uint32_t& r0, uint32_t& r1,
                                       uint32_t& r2, uint32_t& r3, uint32_t addr)
{
    asm volatile("ldmatrix.sync.aligned.m8n8.x4.shared.b16 {%0,%1,%2,%3}, [%4];"
                 : "=r"(r0), "=r"(r1), "=r"(r2), "=r"(r3) : "r"(addr));
}

#define CP_ASYNC16(dst, src) \
    asm volatile("cp.async.cg.shared.global [%0], [%1], 16;" :: "r"(dst), "l"(src))
#define CP_COMMIT() asm volatile("cp.async.commit_group;" ::: "memory")
#define CP_WAIT(n)  asm volatile("cp.async.wait_group %0;" :: "n"(n) : "memory")

#define RED_ADD_F32(addr, val) \
    asm volatile("red.global.add.f32 [%0], %1;" :: "l"(addr), "f"(val) : "memory")

__device__ __forceinline__ uint32_t cvt2h(float a0, float a1) {
    __half2 h = __float22half2_rn(make_float2(a0, a1));
    return *reinterpret_cast<uint32_t*>(&h);
}

// ---------------------------------------------------------------------------
// Kernel 0: convert W to fp16, layout [w][n][k] — COALESCED via smem transpose.
// grid = (EMB/64, 3). Each CTA: load 64(k) x 128(n) fp32 slab coalesced,
// transpose through smem, write 32 contiguous k per thread as 4x uint4.
// ---------------------------------------------------------------------------
__global__ __launch_bounds__(256) void prep_w(
    const float* __restrict__ wq, const float* __restrict__ wk,
    const float* __restrict__ wv)
{
    __shared__ float tile[64 * 128];

    const int tid = threadIdx.x;
    const int kb  = blockIdx.x;          // 0..15 (64 k-rows each)
    const int w   = blockIdx.y;          // 0..2
    const float* W = (w == 0) ? wq : (w == 1) ? wk : wv;
    const int k0 = kb * 64;

    // Coalesced load: 2048 float4, 8 per thread. Row r = 32 float4.
#pragma unroll
    for (int it = 0; it < 8; it++) {
        int u = tid + it * 256;
        int r = u >> 5, c4 = (u & 31) * 4;
        *(float4*)&tile[r * 128 + c4] =
            *(const float4*)&W[(size_t)(k0 + r) * HEAD + c4];
    }
    __syncthreads();

    // Transposed write: thread (n = tid>>1, kh = (tid&1)*32) emits 32 fp16
    // contiguous k-values for its n.
    const int n  = tid >> 1;
    const int kh = (tid & 1) * 32;
    uint32_t packed[16];
#pragma unroll
    for (int i = 0; i < 16; i++)
        packed[i] = cvt2h(tile[(kh + 2 * i) * 128 + n],
                          tile[(kh + 2 * i + 1) * 128 + n]);

    uint4* dst = (uint4*)&g_w[((size_t)w * 128 + n) * 1024 + k0 + kh];
#pragma unroll
    for (int i = 0; i < 4; i++)
        dst[i] = make_uint4(packed[4*i], packed[4*i+1], packed[4*i+2], packed[4*i+3]);
}

// ---------------------------------------------------------------------------
// Kernel 1: projection GEMM  C = A @ W, fp16 single-product.
// ROUND-11 PROVEN VERSION (1 CTA/SM, persistent areg prefetch).
// ---------------------------------------------------------------------------
#define PKPAD 72
#define PABUF (128 * PKPAD * 2)
// smem: A0 0, A1 1, W0 2, W1 3
#define PSM_TOTAL (4 * PABUF)       // 73728

__device__ __forceinline__ void warp_gemm_proj(float acc[4][4][4],
    uint32_t sA, uint32_t sW, uint32_t a_lane, uint32_t b_lane)
{
#pragma unroll
    for (int ks = 0; ks < 4; ks++) {
        const uint32_t kso = (uint32_t)(ks * 16) * 2;
        uint32_t ah[4][4];
#pragma unroll
        for (int mt = 0; mt < 4; mt++) {
            const uint32_t ao = a_lane + (uint32_t)(mt * 16 * PKPAD) * 2 + kso;
            ldm_x4(ah[mt][0], ah[mt][1], ah[mt][2], ah[mt][3], sA + ao);
        }
#pragma unroll
        for (int np = 0; np < 2; np++) {
            const uint32_t bo = b_lane + (uint32_t)(np * 16 * PKPAD) * 2 + kso;
            uint32_t bh[4];
            ldm_x4(bh[0], bh[1], bh[2], bh[3], sW + bo);
#pragma unroll
            for (int mt = 0; mt < 4; mt++) {
                mma16816(acc[mt][2*np],   ah[mt][0], ah[mt][1], ah[mt][2], ah[mt][3], bh[0], bh[1]);
                mma16816(acc[mt][2*np+1], ah[mt][0], ah[mt][1], ah[mt][2], ah[mt][3], bh[2], bh[3]);
            }
        }
    }
}

__global__ __launch_bounds__(256) void proj_tc(
    const float* __restrict__ in_key,
    const float* __restrict__ in_query,
    const float* __restrict__ in_value)
{
    extern __shared__ __align__(16) char psm[];
    const uint32_t sb = smem_u32(psm);

    const float* A;
    const int p = blockIdx.y;
    if (p == 0)      A = in_query;
    else if (p == 1) A = in_key;
    else             A = in_value;

    const int tid  = threadIdx.x;
    const int wid  = tid >> 5, lane = tid & 31;
    const int g    = lane >> 2, t = lane & 3;
    const int mbase = (wid & 1) * 64;
    const int nbase = (wid >> 1) * 32;
    const int tile = blockIdx.x;
    const int rowBase = tile * 128;

    const uint32_t a_lane = ((mbase + (lane & 15)) * PKPAD + (lane >> 4) * 8) * 2;
    const uint32_t b_lane = ((nbase + (lane & 7) + ((lane >> 4) << 3)) * PKPAD
                             + ((lane >> 3) & 1) * 8) * 2;

    const int aRow0 = tid >> 4;
    const int aC4   = (tid & 15) * 4;

    float acc[4][4][4];
#pragma unroll
    for (int i = 0; i < 4; i++)
#pragma unroll
        for (int j = 0; j < 4; j++)
#pragma unroll
            for (int q = 0; q < 4; q++) acc[i][j][q] = 0.0f;

    const __half* wsrc = g_w + (size_t)p * 128 * 1024;

    auto cpa_w = [&](int kb, int s) {
        uint32_t dw = sb + (2 + s) * PABUF;
#pragma unroll
        for (int it = 0; it < 4; it++) {
            int u = tid + it * 256;
            int row = u >> 3, c = u & 7;
            uint32_t doff = (uint32_t)(row * PKPAD + c * 8) * 2;
            size_t soff = (size_t)row * 1024 + kb * 64 + c * 8;
            CP_ASYNC16(dw + doff, (const char*)(wsrc + soff));
        }
        CP_COMMIT();
    };

    auto conv_a = [&](const float4* areg, int s) {
        const uint32_t dA = sb + s * PABUF;
#pragma unroll
        for (int it = 0; it < 8; it++) {
            uint32_t h0 = cvt2h(areg[it].x, areg[it].y);
            uint32_t h1 = cvt2h(areg[it].z, areg[it].w);
            uint32_t doff = (uint32_t)((aRow0 + it * 16) * PKPAD + aC4) * 2;
            asm volatile("st.shared.v2.b32 [%0], {%1,%2};" :: "r"(dA + doff), "r"(h0), "r"(h1));
        }
    };

    float4 areg[8];
#pragma unroll
    for (int it = 0; it < 8; it++)
        areg[it] = *(const float4*)&A[(size_t)(rowBase + aRow0 + it * 16) * EMB + aC4];
    conv_a(areg, 0);
#pragma unroll
    for (int it = 0; it < 8; it++)
        areg[it] = *(const float4*)&A[(size_t)(rowBase + aRow0 + it * 16) * EMB + 64 + aC4];
    cpa_w(0, 0);

    for (int kb = 0; kb < 16; kb++) {
        CP_WAIT(0);
        __syncthreads();

        if (kb < 15) {
            cpa_w(kb + 1, (kb + 1) & 1);
            conv_a(areg, (kb + 1) & 1);
        }
        if (kb < 14) {
            const int k0n = (kb + 2) * 64;
#pragma unroll
            for (int it = 0; it < 8; it++)
                areg[it] = *(const float4*)&A[(size_t)(rowBase + aRow0 + it * 16) * EMB + k0n + aC4];
        }

        const uint32_t sA = sb + (kb & 1) * PABUF;
        const uint32_t sW = sb + (2 + (kb & 1)) * PABUF;
        warp_gemm_proj(acc, sA, sW, a_lane, b_lane);
    }

    const size_t base = (size_t)tile * TILE_ELE;

    if (p != 2) {
        __half* dst = (p == 0) ? g_q : g_k;
#pragma unroll
        for (int mt = 0; mt < 4; mt++)
#pragma unroll
            for (int nt = 0; nt < 4; nt++) {
                int r0 = mbase + mt * 16 + g;
                int c  = nbase + nt * 8 + t * 2;
                *(uint32_t*)(dst + base + (size_t)r0 * 128 + c) =
                    cvt2h(acc[mt][nt][0], acc[mt][nt][1]);
                *(uint32_t*)(dst + base + (size_t)(r0 + 8) * 128 + c) =
                    cvt2h(acc[mt][nt][2], acc[mt][nt][3]);
            }
    } else {
        // V: transposed [h][n]
#pragma unroll
        for (int mt = 0; mt < 4; mt++)
#pragma unroll
            for (int nt = 0; nt < 4; nt++)
#pragma unroll
                for (int q = 0; q < 4; q++) {
                    int row = mbase + mt * 16 + g + (q >> 1) * 8;   // n index
                    int col = nbase + nt * 8 + t * 2 + (q & 1);     // h index
                    g_v[base + (size_t)col * 128 + row] = __float2half(acc[mt][nt][q]);
                }
    }
}

// ---------------------------------------------------------------------------
// Kernel 2: fused causal retention (round-11 proven core, round-13 epilogue).
// ---------------------------------------------------------------------------
#define KPAD 136
#define RB (128 * KPAD * 2)
#define SMR_BYTES (5 * RB)          // 174080: Q, K0, K1, V0, V1

__device__ __forceinline__ void cpa_tile(uint32_t dst, const __half* __restrict__ src,
                                         int tid) {
#pragma unroll
    for (int it = 0; it < 8; it++) {
        int u = tid + it * 256;
        int row = u >> 4, c = u & 15;
        CP_ASYNC16(dst + (uint32_t)(row * KPAD + c * 8) * 2, (const char*)src + (size_t)u * 16);
    }
}

__global__ __launch_bounds__(256) void retention_tc(float* __restrict__ out)
{
    extern __shared__ __align__(16) char smraw[];
    const uint32_t sb = smem_u32(smraw);
    const uint32_t sQ  = sb;
    const uint32_t sK0 = sb + RB;
    const uint32_t sV0 = sb + 3*RB;

    const int tid  = threadIdx.x;
    const int wid  = tid >> 5, lane = tid & 31;
    const int g    = lane >> 2, t = lane & 3;

    const int b   = blockIdx.x;
    const int cid = blockIdx.y;
    const int qt  = c_qt[cid];
    const int j0  = c_j0[cid];
    const int j1  = c_j1[cid];
    const int qtile = b * 16 + qt;

    const uint32_t a_lane = (uint32_t)((16 * wid + (lane & 15)) * KPAD + (lane >> 4) * 8) * 2;
    const uint32_t b_lane = (uint32_t)(((lane & 7) + ((lane >> 4) << 3)) * KPAD
                                       + ((lane >> 3) & 1) * 8) * 2;

    cpa_tile(sQ, g_q + (size_t)qtile * TILE_ELE, tid);
    {
        const size_t kt = (size_t)(b * 16 + j0) * TILE_ELE;
        cpa_tile(sK0 + (uint32_t)(j0 & 1) * RB, g_k + kt, tid);
        cpa_tile(sV0 + (uint32_t)(j0 & 1) * RB, g_v + kt, tid);
    }
    CP_COMMIT();
    CP_WAIT(0);
    __syncthreads();

    float oacc[16][4];
#pragma unroll
    for (int i = 0; i < 16; i++)
#pragma unroll
        for (int q = 0; q < 4; q++) oacc[i][q] = 0.0f;

    for (int j = j0; j < j1; j++) {
        if (j + 1 < j1) {
            const size_t kt = (size_t)(b * 16 + j + 1) * TILE_ELE;
            cpa_tile(sK0 + (uint32_t)((j + 1) & 1) * RB, g_k + kt, tid);
            cpa_tile(sV0 + (uint32_t)((j + 1) & 1) * RB, g_v + kt, tid);
            CP_COMMIT();
        }

        const uint32_t sKc = sK0 + (uint32_t)(j & 1) * RB;
        const uint32_t sVc = sV0 + (uint32_t)(j & 1) * RB;

        // GEMM1: S = Q K^T
        float sacc[16][4];
#pragma unroll
        for (int i = 0; i < 16; i++)
#pragma unroll
            for (int q = 0; q < 4; q++) sacc[i][q] = 0.0f;

#pragma unroll 2
        for (int ks = 0; ks < 8; ks++) {
            const uint32_t kso = (uint32_t)(ks * 16) * 2;
            uint32_t ah[4];
            ldm_x4(ah[0], ah[1], ah[2], ah[3], sQ + a_lane + kso);
#pragma unroll
            for (int nb = 0; nb < 8; nb++) {
                const uint32_t boff = b_lane + (uint32_t)(nb * 16 * KPAD) * 2 + kso;
                uint32_t bh[4];
                ldm_x4(bh[0], bh[1], bh[2], bh[3], sKc + boff);
                mma16816(sacc[2*nb],   ah[0], ah[1], ah[2], ah[3], bh[0], bh[1]);
                mma16816(sacc[2*nb+1], ah[0], ah[1], ah[2], ah[3], bh[2], bh[3]);
            }
        }

        // Causal mask on diagonal tile
        if (j == qt) {
            const int r0 = 16 * wid + g;
#pragma unroll
            for (int nt = 0; nt < 16; nt++) {
                const int c0 = nt * 8 + t * 2;
                if (c0     > r0)     sacc[nt][0] = 0.0f;
                if (c0 + 1 > r0)     sacc[nt][1] = 0.0f;
                if (c0     > r0 + 8) sacc[nt][2] = 0.0f;
                if (c0 + 1 > r0 + 8) sacc[nt][3] = 0.0f;
            }
        }

        // GEMM2: O += S V (S in registers)
#pragma unroll
        for (int ks = 0; ks < 8; ks++) {
            uint32_t sh[4];
            sh[0] = cvt2h(sacc[2*ks][0],   sacc[2*ks][1]);
            sh[1] = cvt2h(sacc[2*ks][2],   sacc[2*ks][3]);
            sh[2] = cvt2h(sacc[2*ks+1][0], sacc[2*ks+1][1]);
            sh[3] = cvt2h(sacc[2*ks+1][2], sacc[2*ks+1][3]);
            const uint32_t kso = (uint32_t)(ks * 16) * 2;
#pragma unroll
            for (int hb = 0; hb < 8; hb++) {
                const uint32_t boff = b_lane + (uint32_t)(hb * 16 * KPAD) * 2 + kso;
                uint32_t vh[4];
                ldm_x4(vh[0], vh[1], vh[2], vh[3], sVc + boff);
                mma16816(oacc[2*hb],   sh[0], sh[1], sh[2], sh[3], vh[0], vh[1]);
                mma16816(oacc[2*hb+1], sh[0], sh[1], sh[2], sh[3], vh[2], vh[3]);
            }
        }

        if (j + 1 < j1) {
            CP_WAIT(0);
            __syncthreads();
        }
    }

    // Epilogue
    const int r0 = 16 * wid + g;
    const size_t rowbase = (size_t)b * SEQ + (size_t)qt * 128;
    if (qt < 8) {
#pragma unroll
        for (int ht = 0; ht < 16; ht++) {
            int c = ht * 8 + t * 2;
            *(float2*)&out[(rowbase + r0) * HEAD + c]     = make_float2(oacc[ht][0], oacc[ht][1]);
            *(float2*)&out[(rowbase + r0 + 8) * HEAD + c] = make_float2(oacc[ht][2], oacc[ht][3]);
        }
    } else {
#pragma unroll
        for (int ht = 0; ht < 16; ht++) {
            int c = ht * 8 + t * 2;
            float* p0 = &out[(rowbase + r0) * HEAD + c];
            float* p1 = &out[(rowbase + r0 + 8) * HEAD + c];
            RED_ADD_F32(p0,     oacc[ht][0]);
            RED_ADD_F32(p0 + 1, oacc[ht][1]);
            RED_ADD_F32(p1,     oacc[ht][2]);
            RED_ADD_F32(p1 + 1, oacc[ht][3]);
        }
    }
}

// ---------------------------------------------------------------------------
// Launch
// ---------------------------------------------------------------------------
extern "C" void kernel_launch(void* const* d_in, const int* in_sizes, int n_in,
                              void* d_out, int out_size)
{
    const float* key   = (const float*)d_in[0];
    const float* query = (const float*)d_in[1];
    const float* value = (const float*)d_in[2];
    const float* w_q   = (const float*)d_in[3];
    const float* w_k   = (const float*)d_in[4];
    const float* w_v   = (const float*)d_in[5];
    float* out = (float*)d_out;

    // Zero-init output: required by the red.add split-K path (qt >= 8 tiles).
    cudaMemsetAsync(out, 0, (size_t)out_size * sizeof(float));

    dim3 gw(EMB / 64, 3);
    prep_w<<<gw, 256>>>(w_q, w_k, w_v);

    cudaFuncSetAttribute(proj_tc,
                         cudaFuncAttributeMaxDynamicSharedMemorySize, PSM_TOTAL);
    dim3 g1(NTILES, 3);
    proj_tc<<<g1, 256, PSM_TOTAL>>>(key, query, value);

    cudaFuncSetAttribute(retention_tc,
                         cudaFuncAttributeMaxDynamicSharedMemorySize, SMR_BYTES);
    dim3 g2(BATCH, 24);
    retention_tc<<<g2, 256, SMR_BYTES>>>(out);
}

// round 16
// speedup vs baseline: 1.0536x; 1.0435x over previous
#include <cuda_runtime.h>
#include <cuda_fp16.h>
#include <cstdint>

// Problem dims
#define BATCH 8
#define SEQ   2048
#define EMB   1024
#define HEAD  128
#define MROWS (BATCH * SEQ)     // 16384
#define NTILES (MROWS / 128)    // 128
#define TILE_ELE (128 * 128)

// fp16 projected tensors, row-major per 128x128 tile.
// Q: [m][h]. K: [n][h]. V: TRANSPOSED [h][n].
__device__ __half g_q[NTILES * TILE_ELE];
__device__ __half g_k[NTILES * TILE_ELE];
__device__ __half g_v[NTILES * TILE_ELE];

// fp16 weights: [w][n][k], k contiguous
__device__ __half g_w[3 * 128 * 1024];

// Perfect-wave schedule: 17 CTAs per batch, each EXACTLY 8 iterations,
// as 1 or 2 segments. Segment 2 always starts at j0=0, j1=qt+1.
__constant__ int s0_qt[17] = {15,15,14,14,13,13,12,12,11,11,10,10, 9, 9, 8, 8, 7};
__constant__ int s0_j0[17] = { 0, 8, 0, 8, 0, 8, 0, 8, 0, 8, 0, 8, 0, 8, 0, 8, 0};
__constant__ int s0_j1[17] = { 8,16, 8,15, 8,14, 8,13, 8,12, 8,11, 8,10, 8, 9, 8};
__constant__ int s1_qt[17] = {-1,-1,-1, 0,-1, 1,-1, 2,-1, 3,-1, 4,-1, 5,-1, 6,-1};

// ---------------------------------------------------------------------------
// PTX helpers (family-generic)
// ---------------------------------------------------------------------------
__device__ __forceinline__ uint32_t smem_u32(const void* p) {
    uint32_t a;
    asm("{ .reg .u64 t; cvta.to.shared.u64 t, %1; cvt.u32.u64 %0, t; }"
        : "=r"(a) : "l"(p));
    return a;
}

__device__ __forceinline__ void mma16816(float* c,
    uint32_t a0, uint32_t a1, uint32_t a2, uint32_t a3,
    uint32_t b0, uint32_t b1)
{
    asm volatile(
        "mma.sync.aligned.m16n8k16.row.col.f32.f16.f16.f32 "
        "{%0,%1,%2,%3}, {%4,%5,%6,%7}, {%8,%9}, {%0,%1,%2,%3};"
        : "+f"(c[0]), "+f"(c[1]), "+f"(c[2]), "+f"(c[3])
        : "r"(a0), "r"(a1), "r"(a2), "r"(a3), "r"(b0), "r"(b1));
}

__device__ __forceinline__ void ldm_x4(uint32_t& r0, uint32_t& r1,
                                       uint32_t& r2, uint32_t& r3, uint32_t addr)
{
    asm volatile("ldmatrix.sync.aligned.m8n8.x4.shared.b16 {%0,%1,%2,%3}, [%4];"
                 : "=r"(r0), "=r"(r1), "=r"(r2), "=r"(r3) : "r"(addr));
}

#define CP_ASYNC16(dst, src) \
    asm volatile("cp.async.cg.shared.global [%0], [%1], 16;" :: "r"(dst), "l"(src))
#define CP_COMMIT() asm volatile("cp.async.commit_group;" ::: "memory")
#define CP_WAIT(n)  asm volatile("cp.async.wait_group %0;" :: "n"(n) : "memory")

#define RED_ADD_F32(addr, val) \
    asm volatile("red.global.add.f32 [%0], %1;" :: "l"(addr), "f"(val) : "memory")

__device__ __forceinline__ uint32_t cvt2h(float a0, float a1) {
    __half2 h = __float22half2_rn(make_float2(a0, a1));
    return *reinterpret_cast<uint32_t*>(&h);
}

// ---------------------------------------------------------------------------
// Kernel 0: convert W to fp16, layout [w][n][k] (coalesced smem transpose).
// ---------------------------------------------------------------------------
__global__ __launch_bounds__(256) void prep_w(
    const float* __restrict__ wq, const float* __restrict__ wk,
    const float* __restrict__ wv)
{
    __shared__ float tile[64 * 128];

    const int tid = threadIdx.x;
    const int kb  = blockIdx.x;
    const int w   = blockIdx.y;
    const float* W = (w == 0) ? wq : (w == 1) ? wk : wv;
    const int k0 = kb * 64;

#pragma unroll
    for (int it = 0; it < 8; it++) {
        int u = tid + it * 256;
        int r = u >> 5, c4 = (u & 31) * 4;
        *(float4*)&tile[r * 128 + c4] =
            *(const float4*)&W[(size_t)(k0 + r) * HEAD + c4];
    }
    __syncthreads();

    const int n  = tid >> 1;
    const int kh = (tid & 1) * 32;
    uint32_t packed[16];
#pragma unroll
    for (int i = 0; i < 16; i++)
        packed[i] = cvt2h(tile[(kh + 2 * i) * 128 + n],
                          tile[(kh + 2 * i + 1) * 128 + n]);

    uint4* dst = (uint4*)&g_w[((size_t)w * 128 + n) * 1024 + k0 + kh];
#pragma unroll
    for (int i = 0; i < 4; i++)
        dst[i] = make_uint4(packed[4*i], packed[4*i+1], packed[4*i+2], packed[4*i+3]);
}

// ---------------------------------------------------------------------------
// Kernel 1: projection GEMM  C = A @ W, fp16 single-product (round-11 proven).
// ---------------------------------------------------------------------------
#define PKPAD 72
#define PABUF (128 * PKPAD * 2)
#define PSM_TOTAL (4 * PABUF)       // 73728

__device__ __forceinline__ void warp_gemm_proj(float acc[4][4][4],
    uint32_t sA, uint32_t sW, uint32_t a_lane, uint32_t b_lane)
{
#pragma unroll
    for (int ks = 0; ks < 4; ks++) {
        const uint32_t kso = (uint32_t)(ks * 16) * 2;
        uint32_t ah[4][4];
#pragma unroll
        for (int mt = 0; mt < 4; mt++) {
            const uint32_t ao = a_lane + (uint32_t)(mt * 16 * PKPAD) * 2 + kso;
            ldm_x4(ah[mt][0], ah[mt][1], ah[mt][2], ah[mt][3], sA + ao);
        }
#pragma unroll
        for (int np = 0; np < 2; np++) {
            const uint32_t bo = b_lane + (uint32_t)(np * 16 * PKPAD) * 2 + kso;
            uint32_t bh[4];
            ldm_x4(bh[0], bh[1], bh[2], bh[3], sW + bo);
#pragma unroll
            for (int mt = 0; mt < 4; mt++) {
                mma16816(acc[mt][2*np],   ah[mt][0], ah[mt][1], ah[mt][2], ah[mt][3], bh[0], bh[1]);
                mma16816(acc[mt][2*np+1], ah[mt][0], ah[mt][1], ah[mt][2], ah[mt][3], bh[2], bh[3]);
            }
        }
    }
}

__global__ __launch_bounds__(256) void proj_tc(
    const float* __restrict__ in_key,
    const float* __restrict__ in_query,
    const float* __restrict__ in_value)
{
    extern __shared__ __align__(16) char psm[];
    const uint32_t sb = smem_u32(psm);

    const float* A;
    const int p = blockIdx.y;
    if (p == 0)      A = in_query;
    else if (p == 1) A = in_key;
    else             A = in_value;

    const int tid  = threadIdx.x;
    const int wid  = tid >> 5, lane = tid & 31;
    const int g    = lane >> 2, t = lane & 3;
    const int mbase = (wid & 1) * 64;
    const int nbase = (wid >> 1) * 32;
    const int tile = blockIdx.x;
    const int rowBase = tile * 128;

    const uint32_t a_lane = ((mbase + (lane & 15)) * PKPAD + (lane >> 4) * 8) * 2;
    const uint32_t b_lane = ((nbase + (lane & 7) + ((lane >> 4) << 3)) * PKPAD
                             + ((lane >> 3) & 1) * 8) * 2;

    const int aRow0 = tid >> 4;
    const int aC4   = (tid & 15) * 4;

    float acc[4][4][4];
#pragma unroll
    for (int i = 0; i < 4; i++)
#pragma unroll
        for (int j = 0; j < 4; j++)
#pragma unroll
            for (int q = 0; q < 4; q++) acc[i][j][q] = 0.0f;

    const __half* wsrc = g_w + (size_t)p * 128 * 1024;

    auto cpa_w = [&](int kb, int s) {
        uint32_t dw = sb + (2 + s) * PABUF;
#pragma unroll
        for (int it = 0; it < 4; it++) {
            int u = tid + it * 256;
            int row = u >> 3, c = u & 7;
            uint32_t doff = (uint32_t)(row * PKPAD + c * 8) * 2;
            size_t soff = (size_t)row * 1024 + kb * 64 + c * 8;
            CP_ASYNC16(dw + doff, (const char*)(wsrc + soff));
        }
        CP_COMMIT();
    };

    auto conv_a = [&](const float4* areg, int s) {
        const uint32_t dA = sb + s * PABUF;
#pragma unroll
        for (int it = 0; it < 8; it++) {
            uint32_t h0 = cvt2h(areg[it].x, areg[it].y);
            uint32_t h1 = cvt2h(areg[it].z, areg[it].w);
            uint32_t doff = (uint32_t)((aRow0 + it * 16) * PKPAD + aC4) * 2;
            asm volatile("st.shared.v2.b32 [%0], {%1,%2};" :: "r"(dA + doff), "r"(h0), "r"(h1));
        }
    };

    float4 areg[8];
#pragma unroll
    for (int it = 0; it < 8; it++)
        areg[it] = *(const float4*)&A[(size_t)(rowBase + aRow0 + it * 16) * EMB + aC4];
    conv_a(areg, 0);
#pragma unroll
    for (int it = 0; it < 8; it++)
        areg[it] = *(const float4*)&A[(size_t)(rowBase + aRow0 + it * 16) * EMB + 64 + aC4];
    cpa_w(0, 0);

    for (int kb = 0; kb < 16; kb++) {
        CP_WAIT(0);
        __syncthreads();

        if (kb < 15) {
            cpa_w(kb + 1, (kb + 1) & 1);
            conv_a(areg, (kb + 1) & 1);
        }
        if (kb < 14) {
            const int k0n = (kb + 2) * 64;
#pragma unroll
            for (int it = 0; it < 8; it++)
                areg[it] = *(const float4*)&A[(size_t)(rowBase + aRow0 + it * 16) * EMB + k0n + aC4];
        }

        const uint32_t sA = sb + (kb & 1) * PABUF;
        const uint32_t sW = sb + (2 + (kb & 1)) * PABUF;
        warp_gemm_proj(acc, sA, sW, a_lane, b_lane);
    }

    const size_t base = (size_t)tile * TILE_ELE;

    if (p != 2) {
        __half* dst = (p == 0) ? g_q : g_k;
#pragma unroll
        for (int mt = 0; mt < 4; mt++)
#pragma unroll
            for (int nt = 0; nt < 4; nt++) {
                int r0 = mbase + mt * 16 + g;
                int c  = nbase + nt * 8 + t * 2;
                *(uint32_t*)(dst + base + (size_t)r0 * 128 + c) =
                    cvt2h(acc[mt][nt][0], acc[mt][nt][1]);
                *(uint32_t*)(dst + base + (size_t)(r0 + 8) * 128 + c) =
                    cvt2h(acc[mt][nt][2], acc[mt][nt][3]);
            }
    } else {
        // V: transposed [h][n]
#pragma unroll
        for (int mt = 0; mt < 4; mt++)
#pragma unroll
            for (int nt = 0; nt < 4; nt++)
#pragma unroll
                for (int q = 0; q < 4; q++) {
                    int row = mbase + mt * 16 + g + (q >> 1) * 8;   // n index
                    int col = nbase + nt * 8 + t * 2 + (q & 1);     // h index
                    g_v[base + (size_t)col * 128 + row] = __float2half(acc[mt][nt][q]);
                }
    }
}

// ---------------------------------------------------------------------------
// Kernel 2: fused causal retention — perfect-wave schedule, up to 2 segments
// per CTA (exactly 8 iterations total). Core loop = round-11 proven.
// ---------------------------------------------------------------------------
#define KPAD 136
#define RB (128 * KPAD * 2)
#define SMR_BYTES (5 * RB)          // 174080: Q, K0, K1, V0, V1

__device__ __forceinline__ void cpa_tile(uint32_t dst, const __half* __restrict__ src,
                                         int tid) {
#pragma unroll
    for (int it = 0; it < 8; it++) {
        int u = tid + it * 256;
        int row = u >> 4, c = u & 15;
        CP_ASYNC16(dst + (uint32_t)(row * KPAD + c * 8) * 2, (const char*)src + (size_t)u * 16);
    }
}

__global__ __launch_bounds__(256) void retention_tc(float* __restrict__ out)
{
    extern __shared__ __align__(16) char smraw[];
    const uint32_t sb = smem_u32(smraw);
    const uint32_t sQ  = sb;
    const uint32_t sK0 = sb + RB;
    const uint32_t sV0 = sb + 3*RB;

    const int tid  = threadIdx.x;
    const int wid  = tid >> 5, lane = tid & 31;
    const int g    = lane >> 2, t = lane & 3;

    const int b   = blockIdx.x;
    const int cid = blockIdx.y;

    const uint32_t a_lane = (uint32_t)((16 * wid + (lane & 15)) * KPAD + (lane >> 4) * 8) * 2;
    const uint32_t b_lane = (uint32_t)(((lane & 7) + ((lane >> 4) << 3)) * KPAD
                                       + ((lane >> 3) & 1) * 8) * 2;

    const int r0 = 16 * wid + g;

#pragma unroll 1
    for (int seg = 0; seg < 2; seg++) {
        int qt, j0, j1;
        if (seg == 0) { qt = s0_qt[cid]; j0 = s0_j0[cid]; j1 = s0_j1[cid]; }
        else          { qt = s1_qt[cid]; j0 = 0; j1 = qt + 1; if (qt < 0) break; }

        const int qtile = b * 16 + qt;

        // Prologue: Q + K(j0) + V(j0) as one group, into stage j0&1.
        cpa_tile(sQ, g_q + (size_t)qtile * TILE_ELE, tid);
        {
            const size_t kt = (size_t)(b * 16 + j0) * TILE_ELE;
            cpa_tile(sK0 + (uint32_t)(j0 & 1) * RB, g_k + kt, tid);
            cpa_tile(sV0 + (uint32_t)(j0 & 1) * RB, g_v + kt, tid);
        }
        CP_COMMIT();
        CP_WAIT(0);
        __syncthreads();

        float oacc[16][4];
#pragma unroll
        for (int i = 0; i < 16; i++)
#pragma unroll
            for (int q = 0; q < 4; q++) oacc[i][q] = 0.0f;

        for (int j = j0; j < j1; j++) {
            if (j + 1 < j1) {
                const size_t kt = (size_t)(b * 16 + j + 1) * TILE_ELE;
                cpa_tile(sK0 + (uint32_t)((j + 1) & 1) * RB, g_k + kt, tid);
                cpa_tile(sV0 + (uint32_t)((j + 1) & 1) * RB, g_v + kt, tid);
                CP_COMMIT();
            }

            const uint32_t sKc = sK0 + (uint32_t)(j & 1) * RB;
            const uint32_t sVc = sV0 + (uint32_t)(j & 1) * RB;

            // GEMM1: S = Q K^T
            float sacc[16][4];
#pragma unroll
            for (int i = 0; i < 16; i++)
#pragma unroll
                for (int q = 0; q < 4; q++) sacc[i][q] = 0.0f;

#pragma unroll 2
            for (int ks = 0; ks < 8; ks++) {
                const uint32_t kso = (uint32_t)(ks * 16) * 2;
                uint32_t ah[4];
                ldm_x4(ah[0], ah[1], ah[2], ah[3], sQ + a_lane + kso);
#pragma unroll
                for (int nb = 0; nb < 8; nb++) {
                    const uint32_t boff = b_lane + (uint32_t)(nb * 16 * KPAD) * 2 + kso;
                    uint32_t bh[4];
                    ldm_x4(bh[0], bh[1], bh[2], bh[3], sKc + boff);
                    mma16816(sacc[2*nb],   ah[0], ah[1], ah[2], ah[3], bh[0], bh[1]);
                    mma16816(sacc[2*nb+1], ah[0], ah[1], ah[2], ah[3], bh[2], bh[3]);
                }
            }

            // Causal mask on diagonal tile
            if (j == qt) {
#pragma unroll
                for (int nt = 0; nt < 16; nt++) {
                    const int c0 = nt * 8 + t * 2;
                    if (c0     > r0)     sacc[nt][0] = 0.0f;
                    if (c0 + 1 > r0)     sacc[nt][1] = 0.0f;
                    if (c0     > r0 + 8) sacc[nt][2] = 0.0f;
                    if (c0 + 1 > r0 + 8) sacc[nt][3] = 0.0f;
                }
            }

            // GEMM2: O += S V (S in registers)
#pragma unroll
            for (int ks = 0; ks < 8; ks++) {
                uint32_t sh[4];
                sh[0] = cvt2h(sacc[2*ks][0],   sacc[2*ks][1]);
                sh[1] = cvt2h(sacc[2*ks][2],   sacc[2*ks][3]);
                sh[2] = cvt2h(sacc[2*ks+1][0], sacc[2*ks+1][1]);
                sh[3] = cvt2h(sacc[2*ks+1][2], sacc[2*ks+1][3]);
                const uint32_t kso = (uint32_t)(ks * 16) * 2;
#pragma unroll
                for (int hb = 0; hb < 8; hb++) {
                    const uint32_t boff = b_lane + (uint32_t)(hb * 16 * KPAD) * 2 + kso;
                    uint32_t vh[4];
                    ldm_x4(vh[0], vh[1], vh[2], vh[3], sVc + boff);
                    mma16816(oacc[2*hb],   sh[0], sh[1], sh[2], sh[3], vh[0], vh[1]);
                    mma16816(oacc[2*hb+1], sh[0], sh[1], sh[2], sh[3], vh[2], vh[3]);
                }
            }

            if (j + 1 < j1) {
                CP_WAIT(0);
                __syncthreads();
            }
        }

        // Epilogue
        const size_t rowbase = (size_t)b * SEQ + (size_t)qt * 128;
        if (qt < 8) {
            // single writer: plain store
#pragma unroll
            for (int ht = 0; ht < 16; ht++) {
                int c = ht * 8 + t * 2;
                *(float2*)&out[(rowbase + r0) * HEAD + c]     = make_float2(oacc[ht][0], oacc[ht][1]);
                *(float2*)&out[(rowbase + r0 + 8) * HEAD + c] = make_float2(oacc[ht][2], oacc[ht][3]);
            }
        } else {
            // two writer chunks: atomic add onto zero-initialized out
#pragma unroll
            for (int ht = 0; ht < 16; ht++) {
                int c = ht * 8 + t * 2;
                float* p0 = &out[(rowbase + r0) * HEAD + c];
                float* p1 = &out[(rowbase + r0 + 8) * HEAD + c];
                RED_ADD_F32(p0,     oacc[ht][0]);
                RED_ADD_F32(p0 + 1, oacc[ht][1]);
                RED_ADD_F32(p1,     oacc[ht][2]);
                RED_ADD_F32(p1 + 1, oacc[ht][3]);
            }
        }

        // Seal all warps' smem reads before next segment's prologue overwrites.
        if (seg == 0 && s1_qt[cid] >= 0) __syncthreads();
    }
}

// ---------------------------------------------------------------------------
// Launch
// ---------------------------------------------------------------------------
extern "C" void kernel_launch(void* const* d_in, const int* in_sizes, int n_in,
                              void* d_out, int out_size)
{
    const float* key   = (const float*)d_in[0];
    const float* query = (const float*)d_in[1];
    const float* value = (const float*)d_in[2];
    const float* w_q   = (const float*)d_in[3];
    const float* w_k   = (const float*)d_in[4];
    const float* w_v   = (const float*)d_in[5];
    float* out = (float*)d_out;

    // Zero-init output: required by the red.add split-K path (qt >= 8 rows).
    cudaMemsetAsync(out, 0, (size_t)out_size * sizeof(float));

    dim3 gw(EMB / 64, 3);
    prep_w<<<gw, 256>>>(w_q, w_k, w_v);

    cudaFuncSetAttribute(proj_tc,
                         cudaFuncAttributeMaxDynamicSharedMemorySize, PSM_TOTAL);
    dim3 g1(NTILES, 3);
    proj_tc<<<g1, 256, PSM_TOTAL>>>(key, query, value);

    cudaFuncSetAttribute(retention_tc,
                         cudaFuncAttributeMaxDynamicSharedMemorySize, SMR_BYTES);
    dim3 g2(BATCH, 17);
    retention_tc<<<g2, 256, SMR_BYTES>>>(out);
}